// round 1
// baseline (speedup 1.0000x reference)
#include <cuda_runtime.h>
#include <math.h>

#define NN 50000
#define EE 800000
#define NF 128
#define NH 8
#define NCH 32
#define F1 256   // NH*NCH
#define NCLS 40

// ---------------- scratch (static device globals; no allocation) ----------------
__device__ float g_h1[NN * F1];
__device__ float g_h2[NN * F1];
__device__ float g_h3[NN * NCLS];
__device__ float g_a1s[NN * NH];
__device__ float g_a1d[NN * NH];
__device__ float g_a2s[NN];
__device__ float g_a2d[NN];
__device__ int   g_deg[NN];
__device__ int   g_rowstart[NN + 1];
__device__ int   g_cursor[NN];
__device__ int   g_csr[EE];
__device__ int   g_is64;

__device__ __forceinline__ float lrelu(float x) { return x > 0.f ? x : 0.2f * x; }

// ---------------- init: zero degree + detect edge_index dtype ----------------
__global__ void k_init(const void* ei) {
    int i = blockIdx.x * blockDim.x + threadIdx.x;
    if (i < NN) g_deg[i] = 0;
    if (i == 0) {
        // if data is really int64, every 8-byte word is a valid node id < NN.
        // if it is int32 pairs, the high word is almost surely nonzero.
        const unsigned long long* p = (const unsigned long long*)ei;
        int ok = 1;
        for (int j = 0; j < 64; j++)
            if (p[j] >= (unsigned long long)NN) ok = 0;
        g_is64 = ok;
    }
}

__device__ __forceinline__ int edge_val(const void* ei, long long idx, int is64) {
    return is64 ? (int)((const long long*)ei)[idx] : ((const int*)ei)[idx];
}

// ---------------- CSR build ----------------
__global__ void k_deg(const void* ei) {
    int e = blockIdx.x * blockDim.x + threadIdx.x;
    if (e >= EE) return;
    int is64 = g_is64;
    int d = edge_val(ei, (long long)EE + e, is64);
    atomicAdd(&g_deg[d], 1);
}

__global__ void k_scan() {   // single block, 1024 threads
    __shared__ int sh[1024];
    const int ITEMS = 49;    // 1024*49 = 50176 >= NN
    int tid = threadIdx.x;
    int start = tid * ITEMS;
    int lsum = 0;
    for (int i = 0; i < ITEMS; i++) {
        int idx = start + i;
        if (idx < NN) lsum += g_deg[idx];
    }
    sh[tid] = lsum;
    __syncthreads();
    for (int off = 1; off < 1024; off <<= 1) {
        int t = (tid >= off) ? sh[tid - off] : 0;
        __syncthreads();
        sh[tid] += t;
        __syncthreads();
    }
    int run = sh[tid] - lsum;  // exclusive prefix
    for (int i = 0; i < ITEMS; i++) {
        int idx = start + i;
        if (idx < NN) {
            g_rowstart[idx] = run;
            g_cursor[idx]   = run;
            run += g_deg[idx];
        }
    }
    if (tid == 1023) g_rowstart[NN] = sh[1023];
}

__global__ void k_scatter(const void* ei) {
    int e = blockIdx.x * blockDim.x + threadIdx.x;
    if (e >= EE) return;
    int is64 = g_is64;
    int s = edge_val(ei, e, is64);
    int d = edge_val(ei, (long long)EE + e, is64);
    int pos = atomicAdd(&g_cursor[d], 1);
    g_csr[pos] = s;
}

// ---------------- GEMM1: h1 = x @ W1  [NN,128]x[128,256] ----------------
// block: 64 rows x 256 cols, 256 threads, 8x8 per thread, BK=32
__global__ __launch_bounds__(256) void k_gemm1(const float* __restrict__ x,
                                               const float* __restrict__ W) {
    __shared__ float xs[32][65];
    __shared__ float ws[32][256];
    int tid = threadIdx.x;
    int tx = tid & 31, ty = tid >> 5;
    int m0 = blockIdx.x * 64;
    float acc[8][8];
#pragma unroll
    for (int i = 0; i < 8; i++)
#pragma unroll
        for (int j = 0; j < 8; j++) acc[i][j] = 0.f;

    for (int ks = 0; ks < NF; ks += 32) {
        // x tile: 64 rows x 32 k (transposed into xs[k][row])
        {
            int r  = tid >> 2;
            int c4 = (tid & 3) << 3;
            int gm = m0 + r;
            float4 v0, v1;
            if (gm < NN) {
                const float4* px = (const float4*)(x + (long long)gm * NF + ks + c4);
                v0 = px[0]; v1 = px[1];
            } else {
                v0 = make_float4(0, 0, 0, 0); v1 = v0;
            }
            xs[c4 + 0][r] = v0.x; xs[c4 + 1][r] = v0.y;
            xs[c4 + 2][r] = v0.z; xs[c4 + 3][r] = v0.w;
            xs[c4 + 4][r] = v1.x; xs[c4 + 5][r] = v1.y;
            xs[c4 + 6][r] = v1.z; xs[c4 + 7][r] = v1.w;
        }
        // W tile: 32 x 256
#pragma unroll
        for (int it = 0; it < 8; it++) {
            int f4 = it * 256 + tid;
            int k = f4 >> 6, c4 = f4 & 63;
            float4 wv = ((const float4*)(W + (long long)(ks + k) * F1))[c4];
            *((float4*)&ws[k][c4 << 2]) = wv;
        }
        __syncthreads();
#pragma unroll
        for (int k = 0; k < 32; k++) {
            float a[8], b[8];
#pragma unroll
            for (int i = 0; i < 8; i++) a[i] = xs[k][ty + 8 * i];
#pragma unroll
            for (int j = 0; j < 8; j++) b[j] = ws[k][tx + 32 * j];
#pragma unroll
            for (int i = 0; i < 8; i++)
#pragma unroll
                for (int j = 0; j < 8; j++) acc[i][j] = fmaf(a[i], b[j], acc[i][j]);
        }
        __syncthreads();
    }
#pragma unroll
    for (int i = 0; i < 8; i++) {
        int gm = m0 + ty + 8 * i;
        if (gm < NN) {
#pragma unroll
            for (int j = 0; j < 8; j++)
                g_h1[(long long)gm * F1 + tx + 32 * j] = acc[i][j];
        }
    }
}

// ---------------- attention logits layer 1 ----------------
__global__ __launch_bounds__(256) void k_att1(const float* __restrict__ asw,
                                              const float* __restrict__ adw) {
    int n = blockIdx.x;
    int t = threadIdx.x;  // head = t/32, c = t%32, warp == head
    float h = g_h1[(long long)n * F1 + t];
    float vs = h * asw[t];
    float vd = h * adw[t];
#pragma unroll
    for (int o = 16; o; o >>= 1) {
        vs += __shfl_down_sync(0xffffffffu, vs, o);
        vd += __shfl_down_sync(0xffffffffu, vd, o);
    }
    if ((t & 31) == 0) {
        g_a1s[n * NH + (t >> 5)] = vs;
        g_a1d[n * NH + (t >> 5)] = vd;
    }
}

// ---------------- layer-1 edge softmax + aggregation + bias + ELU ----------------
__global__ __launch_bounds__(256) void k_agg1(const float* __restrict__ b1) {
    int n = blockIdx.x;
    int tid = threadIdx.x;
    int head = tid >> 5;
    __shared__ float sdst[NH], ssrcn[NH], sm[NH], sinv[NH];
    __shared__ float wred[8][NH];
    __shared__ float alpha_sh[32 * NH];
    __shared__ int   src_sh[32];

    if (tid < NH) {
        sdst[tid]  = g_a1d[n * NH + tid];
        ssrcn[tid] = g_a1s[n * NH + tid];
    }
    __syncthreads();
    int rs = g_rowstart[n], re = g_rowstart[n + 1];

    // phase 1: per-head max (self-loop included in init)
    float mx[NH];
#pragma unroll
    for (int h = 0; h < NH; h++) mx[h] = lrelu(ssrcn[h] + sdst[h]);
    for (int e = rs + tid; e < re; e += 256) {
        int s = g_csr[e];
        const float* ps = g_a1s + (long long)s * NH;
#pragma unroll
        for (int h = 0; h < NH; h++) mx[h] = fmaxf(mx[h], lrelu(ps[h] + sdst[h]));
    }
#pragma unroll
    for (int h = 0; h < NH; h++)
#pragma unroll
        for (int o = 16; o; o >>= 1) mx[h] = fmaxf(mx[h], __shfl_down_sync(0xffffffffu, mx[h], o));
    if ((tid & 31) == 0)
#pragma unroll
        for (int h = 0; h < NH; h++) wred[tid >> 5][h] = mx[h];
    __syncthreads();
    if (tid < NH) {
        float m = wred[0][tid];
#pragma unroll
        for (int w = 1; w < 8; w++) m = fmaxf(m, wred[w][tid]);
        sm[tid] = m;
    }
    __syncthreads();

    // phase 2: per-head sum of exp
    float sum[NH];
#pragma unroll
    for (int h = 0; h < NH; h++)
        sum[h] = (tid == 0) ? __expf(lrelu(ssrcn[h] + sdst[h]) - sm[h]) : 0.f;
    for (int e = rs + tid; e < re; e += 256) {
        int s = g_csr[e];
        const float* ps = g_a1s + (long long)s * NH;
#pragma unroll
        for (int h = 0; h < NH; h++) sum[h] += __expf(lrelu(ps[h] + sdst[h]) - sm[h]);
    }
#pragma unroll
    for (int h = 0; h < NH; h++)
#pragma unroll
        for (int o = 16; o; o >>= 1) sum[h] += __shfl_down_sync(0xffffffffu, sum[h], o);
    if ((tid & 31) == 0)
#pragma unroll
        for (int h = 0; h < NH; h++) wred[tid >> 5][h] = sum[h];
    __syncthreads();
    if (tid < NH) {
        float s = 0.f;
#pragma unroll
        for (int w = 0; w < 8; w++) s += wred[w][tid];
        sinv[tid] = 1.f / (s + 1e-16f);
    }
    __syncthreads();

    // phase 3: weighted gather (thread tid = channel tid)
    float acc;
    {
        float lself = lrelu(ssrcn[head] + sdst[head]);
        float aself = __expf(lself - sm[head]) * sinv[head];
        acc = aself * g_h1[(long long)n * F1 + tid];
    }
    for (int base = rs; base < re; base += 32) {
        int cnt = min(32, re - base);
        __syncthreads();
        if (tid < cnt * 8) {
            int el = tid >> 3, h = tid & 7;
            int s = g_csr[base + el];
            if (h == 0) src_sh[el] = s;
            float v = lrelu(g_a1s[(long long)s * NH + h] + sdst[h]);
            alpha_sh[el * NH + h] = __expf(v - sm[h]) * sinv[h];
        }
        __syncthreads();
#pragma unroll 4
        for (int e = 0; e < cnt; e++)
            acc = fmaf(alpha_sh[e * NH + head], g_h1[(long long)src_sh[e] * F1 + tid], acc);
    }
    float v = acc + b1[tid];
    g_h2[(long long)n * F1 + tid] = (v > 0.f) ? v : expm1f(v);
}

// ---------------- GEMM2: h3 = h2 @ W2  [NN,256]x[256,40] + a2 logits ----------------
// block: 128 rows x 40 cols, 256 threads (tx=tid&7 cols, ty=tid>>3 rows), 4x5 per thread
__global__ __launch_bounds__(256) void k_gemm2(const float* __restrict__ W2,
                                               const float* __restrict__ a2sw,
                                               const float* __restrict__ a2dw) {
    __shared__ float hs[32][129];
    __shared__ float ws2[32][40];
    int tid = threadIdx.x;
    int tx = tid & 7, ty = tid >> 3;
    int m0 = blockIdx.x * 128;
    float acc[4][5];
#pragma unroll
    for (int i = 0; i < 4; i++)
#pragma unroll
        for (int j = 0; j < 5; j++) acc[i][j] = 0.f;

    for (int ks = 0; ks < F1; ks += 32) {
#pragma unroll
        for (int it = 0; it < 4; it++) {
            int f4 = it * 256 + tid;
            int r = f4 >> 3, c4 = f4 & 7;
            int gm = m0 + r;
            float4 v = make_float4(0, 0, 0, 0);
            if (gm < NN) v = *((const float4*)(g_h2 + (long long)gm * F1 + ks + (c4 << 2)));
            hs[(c4 << 2) + 0][r] = v.x; hs[(c4 << 2) + 1][r] = v.y;
            hs[(c4 << 2) + 2][r] = v.z; hs[(c4 << 2) + 3][r] = v.w;
        }
#pragma unroll
        for (int it = 0; it < 5; it++) {
            int idx = it * 256 + tid;   // 0..1279
            int k = idx / 40, c = idx % 40;
            ws2[k][c] = W2[(long long)(ks + k) * NCLS + c];
        }
        __syncthreads();
#pragma unroll
        for (int k = 0; k < 32; k++) {
            float a[4], b[5];
#pragma unroll
            for (int i = 0; i < 4; i++) a[i] = hs[k][ty + 32 * i];
#pragma unroll
            for (int j = 0; j < 5; j++) b[j] = ws2[k][tx + 8 * j];
#pragma unroll
            for (int i = 0; i < 4; i++)
#pragma unroll
                for (int j = 0; j < 5; j++) acc[i][j] = fmaf(a[i], b[j], acc[i][j]);
        }
        __syncthreads();
    }
#pragma unroll
    for (int i = 0; i < 4; i++) {
        int gm = m0 + ty + 32 * i;
        if (gm >= NN) continue;
        float pa = 0.f, pd = 0.f;
#pragma unroll
        for (int j = 0; j < 5; j++) {
            int c = tx + 8 * j;
            g_h3[(long long)gm * NCLS + c] = acc[i][j];
            pa = fmaf(acc[i][j], a2sw[c], pa);
            pd = fmaf(acc[i][j], a2dw[c], pd);
        }
#pragma unroll
        for (int o = 4; o; o >>= 1) {   // segmented reduce over the 8 tx lanes
            pa += __shfl_down_sync(0xffffffffu, pa, o, 8);
            pd += __shfl_down_sync(0xffffffffu, pd, o, 8);
        }
        if (tx == 0) { g_a2s[gm] = pa; g_a2d[gm] = pd; }
    }
}

// ---------------- layer-2 aggregation + bias + log_softmax ----------------
__global__ __launch_bounds__(64) void k_agg2(const float* __restrict__ b2,
                                             float* __restrict__ out) {
    int n = blockIdx.x;
    int tid = threadIdx.x;   // 64 threads
    __shared__ float sh[64];
    __shared__ float alpha_sh[64];
    __shared__ int   src_sh[64];
    __shared__ float s_m, s_inv;

    float adn = g_a2d[n];
    float asn = g_a2s[n];
    int rs = g_rowstart[n], re = g_rowstart[n + 1];
    float lself = lrelu(asn + adn);

    float mx = lself;
    for (int e = rs + tid; e < re; e += 64)
        mx = fmaxf(mx, lrelu(g_a2s[g_csr[e]] + adn));
#pragma unroll
    for (int o = 16; o; o >>= 1) mx = fmaxf(mx, __shfl_down_sync(0xffffffffu, mx, o));
    if ((tid & 31) == 0) sh[tid >> 5] = mx;
    __syncthreads();
    if (tid == 0) s_m = fmaxf(sh[0], sh[1]);
    __syncthreads();
    float m = s_m;

    float sum = (tid == 0) ? __expf(lself - m) : 0.f;
    for (int e = rs + tid; e < re; e += 64)
        sum += __expf(lrelu(g_a2s[g_csr[e]] + adn) - m);
#pragma unroll
    for (int o = 16; o; o >>= 1) sum += __shfl_down_sync(0xffffffffu, sum, o);
    if ((tid & 31) == 0) sh[tid >> 5] = sum;
    __syncthreads();
    if (tid == 0) s_inv = 1.f / (sh[0] + sh[1] + 1e-16f);
    __syncthreads();
    float inv = s_inv;

    float acc = 0.f;
    if (tid < NCLS)
        acc = __expf(lself - m) * inv * g_h3[(long long)n * NCLS + tid];
    for (int base = rs; base < re; base += 64) {
        int cnt = min(64, re - base);
        __syncthreads();
        if (tid < cnt) {
            int s = g_csr[base + tid];
            src_sh[tid] = s;
            alpha_sh[tid] = __expf(lrelu(g_a2s[s] + adn) - m) * inv;
        }
        __syncthreads();
        if (tid < NCLS) {
#pragma unroll 4
            for (int e = 0; e < cnt; e++)
                acc = fmaf(alpha_sh[e], g_h3[(long long)src_sh[e] * NCLS + tid], acc);
        }
    }

    // fused log_softmax over 40 classes
    __syncthreads();
    if (tid < NCLS) sh[tid] = acc + b2[tid];
    __syncthreads();
    float v = 0.f, mm = 0.f;
    if (tid < NCLS) {
        v = sh[tid];
        mm = sh[0];
#pragma unroll
        for (int i = 1; i < NCLS; i++) mm = fmaxf(mm, sh[i]);
        alpha_sh[tid] = __expf(v - mm);
    }
    __syncthreads();
    if (tid < NCLS) {
        float s = 0.f;
#pragma unroll
        for (int i = 0; i < NCLS; i++) s += alpha_sh[i];
        out[(long long)n * NCLS + tid] = v - mm - logf(s);
    }
}

// ---------------- launcher ----------------
extern "C" void kernel_launch(void* const* d_in, const int* in_sizes, int n_in,
                              void* d_out, int out_size) {
    const float* x   = (const float*)d_in[0];
    const void*  ei  = d_in[1];
    const float* W1  = (const float*)d_in[2];
    const float* a1s = (const float*)d_in[3];
    const float* a1d = (const float*)d_in[4];
    const float* b1  = (const float*)d_in[5];
    const float* W2  = (const float*)d_in[6];
    const float* a2s = (const float*)d_in[7];
    const float* a2d = (const float*)d_in[8];
    const float* b2  = (const float*)d_in[9];
    float* out = (float*)d_out;

    k_init<<<(NN + 255) / 256, 256>>>(ei);
    k_deg<<<(EE + 255) / 256, 256>>>(ei);
    k_scan<<<1, 1024>>>();
    k_scatter<<<(EE + 255) / 256, 256>>>(ei);
    k_gemm1<<<(NN + 63) / 64, 256>>>(x, W1);
    k_att1<<<NN, 256>>>(a1s, a1d);
    k_agg1<<<NN, 256>>>(b1);
    k_gemm2<<<(NN + 127) / 128, 256>>>(W2, a2s, a2d);
    k_agg2<<<NN, 64>>>(b2, out);
}

// round 2
// speedup vs baseline: 1.0638x; 1.0638x over previous
#include <cuda_runtime.h>
#include <math.h>

#define NN 50000
#define EE 800000
#define NF 128
#define NH 8
#define F1 256   // NH*NCH
#define NCLS 40

// ---------------- scratch (static device globals; no allocation) ----------------
__device__ float g_h1[NN * F1];
__device__ float g_h2[NN * F1];
__device__ float g_h3[NN * NCLS];
__device__ float g_a1s[NN * NH];
__device__ float g_a1d[NN * NH];
__device__ float g_m1[NN * NH];
__device__ float g_s1[NN * NH];
__device__ float g_a2s[NN];
__device__ float g_a2d[NN];
__device__ float g_m2[NN];
__device__ float g_s2[NN];
__device__ float g_alpha1[(size_t)EE * NH];
__device__ float g_alpha2[EE];
__device__ int   g_deg[NN];
__device__ int   g_rowstart[NN + 1];
__device__ int   g_cursor[NN];
__device__ int   g_csr[EE];
__device__ int   g_edst[EE];
__device__ int   g_is64;

__device__ __forceinline__ float lrelu(float x) { return x > 0.f ? x : 0.2f * x; }

__device__ __forceinline__ void atomicMaxF(float* addr, float v) {
    if (v >= 0.f) atomicMax((int*)addr, __float_as_int(v));
    else          atomicMin((unsigned int*)addr, __float_as_uint(v));
}

// ---------------- init: zero accumulators + detect edge_index dtype ----------------
__global__ void k_init(const void* ei) {
    int i = blockIdx.x * blockDim.x + threadIdx.x;
    if (i < NN * NH) g_s1[i] = 0.f;
    if (i < NN) { g_deg[i] = 0; g_s2[i] = 0.f; }
    if (i == 0) {
        const unsigned long long* p = (const unsigned long long*)ei;
        int ok = 1;
        for (int j = 0; j < 64; j++)
            if (p[j] >= (unsigned long long)NN) ok = 0;
        g_is64 = ok;
    }
}

__device__ __forceinline__ int edge_val(const void* ei, long long idx, int is64) {
    return is64 ? (int)((const long long*)ei)[idx] : ((const int*)ei)[idx];
}

// ---------------- CSR build ----------------
__global__ void k_deg(const void* ei) {
    int e = blockIdx.x * blockDim.x + threadIdx.x;
    if (e >= EE) return;
    int d = edge_val(ei, (long long)EE + e, g_is64);
    atomicAdd(&g_deg[d], 1);
}

__global__ void k_scan() {   // single block, 1024 threads
    __shared__ int sh[1024];
    const int ITEMS = 49;    // 1024*49 = 50176 >= NN
    int tid = threadIdx.x;
    int start = tid * ITEMS;
    int lsum = 0;
    for (int i = 0; i < ITEMS; i++) {
        int idx = start + i;
        if (idx < NN) lsum += g_deg[idx];
    }
    sh[tid] = lsum;
    __syncthreads();
    for (int off = 1; off < 1024; off <<= 1) {
        int t = (tid >= off) ? sh[tid - off] : 0;
        __syncthreads();
        sh[tid] += t;
        __syncthreads();
    }
    int run = sh[tid] - lsum;  // exclusive prefix
    for (int i = 0; i < ITEMS; i++) {
        int idx = start + i;
        if (idx < NN) {
            g_rowstart[idx] = run;
            g_cursor[idx]   = run;
            run += g_deg[idx];
        }
    }
    if (tid == 1023) g_rowstart[NN] = sh[1023];
}

__global__ void k_scatter(const void* ei) {
    int e = blockIdx.x * blockDim.x + threadIdx.x;
    if (e >= EE) return;
    int is64 = g_is64;
    int s = edge_val(ei, e, is64);
    int d = edge_val(ei, (long long)EE + e, is64);
    int pos = atomicAdd(&g_cursor[d], 1);
    g_csr[pos]  = s;
    g_edst[pos] = d;
}

// ---------------- GEMM1: h1 = x @ W1  [NN,128]x[128,256] ----------------
__global__ __launch_bounds__(256) void k_gemm1(const float* __restrict__ x,
                                               const float* __restrict__ W) {
    __shared__ float xs[32][65];
    __shared__ float ws[32][256];
    int tid = threadIdx.x;
    int tx = tid & 31, ty = tid >> 5;
    int m0 = blockIdx.x * 64;
    float acc[8][8];
#pragma unroll
    for (int i = 0; i < 8; i++)
#pragma unroll
        for (int j = 0; j < 8; j++) acc[i][j] = 0.f;

    for (int ks = 0; ks < NF; ks += 32) {
        {
            int r  = tid >> 2;
            int c4 = (tid & 3) << 3;
            int gm = m0 + r;
            float4 v0, v1;
            if (gm < NN) {
                const float4* px = (const float4*)(x + (long long)gm * NF + ks + c4);
                v0 = px[0]; v1 = px[1];
            } else {
                v0 = make_float4(0, 0, 0, 0); v1 = v0;
            }
            xs[c4 + 0][r] = v0.x; xs[c4 + 1][r] = v0.y;
            xs[c4 + 2][r] = v0.z; xs[c4 + 3][r] = v0.w;
            xs[c4 + 4][r] = v1.x; xs[c4 + 5][r] = v1.y;
            xs[c4 + 6][r] = v1.z; xs[c4 + 7][r] = v1.w;
        }
#pragma unroll
        for (int it = 0; it < 8; it++) {
            int f4 = it * 256 + tid;
            int k = f4 >> 6, c4 = f4 & 63;
            float4 wv = ((const float4*)(W + (long long)(ks + k) * F1))[c4];
            *((float4*)&ws[k][c4 << 2]) = wv;
        }
        __syncthreads();
#pragma unroll
        for (int k = 0; k < 32; k++) {
            float a[8], b[8];
#pragma unroll
            for (int i = 0; i < 8; i++) a[i] = xs[k][ty + 8 * i];
#pragma unroll
            for (int j = 0; j < 8; j++) b[j] = ws[k][tx + 32 * j];
#pragma unroll
            for (int i = 0; i < 8; i++)
#pragma unroll
                for (int j = 0; j < 8; j++) acc[i][j] = fmaf(a[i], b[j], acc[i][j]);
        }
        __syncthreads();
    }
#pragma unroll
    for (int i = 0; i < 8; i++) {
        int gm = m0 + ty + 8 * i;
        if (gm < NN) {
#pragma unroll
            for (int j = 0; j < 8; j++)
                g_h1[(long long)gm * F1 + tx + 32 * j] = acc[i][j];
        }
    }
}

// ---------------- attention logits layer 1 (+ m1 init with self-loop) ----------------
__global__ __launch_bounds__(256) void k_att1(const float* __restrict__ asw,
                                              const float* __restrict__ adw) {
    int n = blockIdx.x;
    int t = threadIdx.x;  // head = t/32, warp == head
    float h = g_h1[(long long)n * F1 + t];
    float vs = h * asw[t];
    float vd = h * adw[t];
#pragma unroll
    for (int o = 16; o; o >>= 1) {
        vs += __shfl_down_sync(0xffffffffu, vs, o);
        vd += __shfl_down_sync(0xffffffffu, vd, o);
    }
    if ((t & 31) == 0) {
        int hh = t >> 5;
        g_a1s[n * NH + hh] = vs;
        g_a1d[n * NH + hh] = vd;
        g_m1[n * NH + hh]  = lrelu(vs + vd);   // self-loop initializes the max
    }
}

// ---------------- edge-parallel max (layer 1) ----------------
__global__ void k_emax1() {
    int e = blockIdx.x * blockDim.x + threadIdx.x;
    if (e >= EE) return;
    int s = g_csr[e], d = g_edst[e];
    const float4* ps = (const float4*)(g_a1s + s * NH);
    const float4* pd = (const float4*)(g_a1d + d * NH);
    float4 s0 = ps[0], s1 = ps[1], d0 = pd[0], d1 = pd[1];
    float l[8];
    l[0] = lrelu(s0.x + d0.x); l[1] = lrelu(s0.y + d0.y);
    l[2] = lrelu(s0.z + d0.z); l[3] = lrelu(s0.w + d0.w);
    l[4] = lrelu(s1.x + d1.x); l[5] = lrelu(s1.y + d1.y);
    l[6] = lrelu(s1.z + d1.z); l[7] = lrelu(s1.w + d1.w);
#pragma unroll
    for (int h = 0; h < NH; h++) atomicMaxF(&g_m1[d * NH + h], l[h]);
}

// ---------------- edge-parallel exp + sum (layer 1) ----------------
__global__ void k_esum1() {
    int e = blockIdx.x * blockDim.x + threadIdx.x;
    if (e >= EE) return;
    int s = g_csr[e], d = g_edst[e];
    const float4* ps = (const float4*)(g_a1s + s * NH);
    const float4* pd = (const float4*)(g_a1d + d * NH);
    const float4* pm = (const float4*)(g_m1 + d * NH);
    float4 s0 = ps[0], s1 = ps[1], d0 = pd[0], d1 = pd[1], m0 = pm[0], m1 = pm[1];
    float a[8];
    a[0] = __expf(lrelu(s0.x + d0.x) - m0.x);
    a[1] = __expf(lrelu(s0.y + d0.y) - m0.y);
    a[2] = __expf(lrelu(s0.z + d0.z) - m0.z);
    a[3] = __expf(lrelu(s0.w + d0.w) - m0.w);
    a[4] = __expf(lrelu(s1.x + d1.x) - m1.x);
    a[5] = __expf(lrelu(s1.y + d1.y) - m1.y);
    a[6] = __expf(lrelu(s1.z + d1.z) - m1.z);
    a[7] = __expf(lrelu(s1.w + d1.w) - m1.w);
    float4* pa = (float4*)(g_alpha1 + (size_t)e * NH);
    pa[0] = make_float4(a[0], a[1], a[2], a[3]);
    pa[1] = make_float4(a[4], a[5], a[6], a[7]);
#pragma unroll
    for (int h = 0; h < NH; h++) atomicAdd(&g_s1[d * NH + h], a[h]);
}

// ---------------- layer-1 gather: h2 = ELU(agg + b1) ----------------
__global__ __launch_bounds__(256) void k_gather1(const float* __restrict__ b1) {
    int n = blockIdx.x;
    int tid = threadIdx.x;
    int h = tid >> 5;          // head, uniform per warp
    float as = g_a1s[n * NH + h];
    float ad = g_a1d[n * NH + h];
    float m  = g_m1[n * NH + h];
    float selfw = __expf(lrelu(as + ad) - m);
    float sinv  = 1.f / (g_s1[n * NH + h] + selfw + 1e-16f);
    float acc = selfw * g_h1[n * F1 + tid];
    int rs = g_rowstart[n], re = g_rowstart[n + 1];
    int e = rs;
    for (; e + 4 <= re; e += 4) {
        int s0 = g_csr[e], s1 = g_csr[e + 1], s2 = g_csr[e + 2], s3 = g_csr[e + 3];
        float a0 = g_alpha1[(size_t)e * NH + h];
        float a1 = g_alpha1[(size_t)(e + 1) * NH + h];
        float a2 = g_alpha1[(size_t)(e + 2) * NH + h];
        float a3 = g_alpha1[(size_t)(e + 3) * NH + h];
        float v0 = g_h1[s0 * F1 + tid];
        float v1 = g_h1[s1 * F1 + tid];
        float v2 = g_h1[s2 * F1 + tid];
        float v3 = g_h1[s3 * F1 + tid];
        acc = fmaf(a0, v0, acc);
        acc = fmaf(a1, v1, acc);
        acc = fmaf(a2, v2, acc);
        acc = fmaf(a3, v3, acc);
    }
    for (; e < re; e++)
        acc = fmaf(g_alpha1[(size_t)e * NH + h], g_h1[g_csr[e] * F1 + tid], acc);
    float v = acc * sinv + b1[tid];
    g_h2[n * F1 + tid] = (v > 0.f) ? v : expm1f(v);
}

// ---------------- GEMM2: h3 = h2 @ W2 + a2 logits + m2 init ----------------
__global__ __launch_bounds__(256) void k_gemm2(const float* __restrict__ W2,
                                               const float* __restrict__ a2sw,
                                               const float* __restrict__ a2dw) {
    __shared__ float hs[32][129];
    __shared__ float ws2[32][40];
    int tid = threadIdx.x;
    int tx = tid & 7, ty = tid >> 3;
    int m0 = blockIdx.x * 128;
    float acc[4][5];
#pragma unroll
    for (int i = 0; i < 4; i++)
#pragma unroll
        for (int j = 0; j < 5; j++) acc[i][j] = 0.f;

    for (int ks = 0; ks < F1; ks += 32) {
#pragma unroll
        for (int it = 0; it < 4; it++) {
            int f4 = it * 256 + tid;
            int r = f4 >> 3, c4 = f4 & 7;
            int gm = m0 + r;
            float4 v = make_float4(0, 0, 0, 0);
            if (gm < NN) v = *((const float4*)(g_h2 + (long long)gm * F1 + ks + (c4 << 2)));
            hs[(c4 << 2) + 0][r] = v.x; hs[(c4 << 2) + 1][r] = v.y;
            hs[(c4 << 2) + 2][r] = v.z; hs[(c4 << 2) + 3][r] = v.w;
        }
#pragma unroll
        for (int it = 0; it < 5; it++) {
            int idx = it * 256 + tid;
            int k = idx / 40, c = idx % 40;
            ws2[k][c] = W2[(long long)(ks + k) * NCLS + c];
        }
        __syncthreads();
#pragma unroll
        for (int k = 0; k < 32; k++) {
            float a[4], b[5];
#pragma unroll
            for (int i = 0; i < 4; i++) a[i] = hs[k][ty + 32 * i];
#pragma unroll
            for (int j = 0; j < 5; j++) b[j] = ws2[k][tx + 8 * j];
#pragma unroll
            for (int i = 0; i < 4; i++)
#pragma unroll
                for (int j = 0; j < 5; j++) acc[i][j] = fmaf(a[i], b[j], acc[i][j]);
        }
        __syncthreads();
    }
#pragma unroll
    for (int i = 0; i < 4; i++) {
        int gm = m0 + ty + 32 * i;
        if (gm >= NN) continue;
        float pa = 0.f, pd = 0.f;
#pragma unroll
        for (int j = 0; j < 5; j++) {
            int c = tx + 8 * j;
            g_h3[(long long)gm * NCLS + c] = acc[i][j];
            pa = fmaf(acc[i][j], a2sw[c], pa);
            pd = fmaf(acc[i][j], a2dw[c], pd);
        }
#pragma unroll
        for (int o = 4; o; o >>= 1) {
            pa += __shfl_down_sync(0xffffffffu, pa, o, 8);
            pd += __shfl_down_sync(0xffffffffu, pd, o, 8);
        }
        if (tx == 0) {
            g_a2s[gm] = pa;
            g_a2d[gm] = pd;
            g_m2[gm]  = lrelu(pa + pd);   // self-loop init
        }
    }
}

// ---------------- edge-parallel max / sum (layer 2) ----------------
__global__ void k_emax2() {
    int e = blockIdx.x * blockDim.x + threadIdx.x;
    if (e >= EE) return;
    int s = g_csr[e], d = g_edst[e];
    atomicMaxF(&g_m2[d], lrelu(g_a2s[s] + g_a2d[d]));
}

__global__ void k_esum2() {
    int e = blockIdx.x * blockDim.x + threadIdx.x;
    if (e >= EE) return;
    int s = g_csr[e], d = g_edst[e];
    float a = __expf(lrelu(g_a2s[s] + g_a2d[d]) - g_m2[d]);
    g_alpha2[e] = a;
    atomicAdd(&g_s2[d], a);
}

// ---------------- layer-2 gather + log_softmax (one warp per node) ----------------
__global__ __launch_bounds__(128) void k_gather2(const float* __restrict__ b2,
                                                 float* __restrict__ out) {
    int n = blockIdx.x * 4 + (threadIdx.x >> 5);
    if (n >= NN) return;
    int tid = threadIdx.x & 31;
    float m = g_m2[n];
    float lself = lrelu(g_a2s[n] + g_a2d[n]);
    float selfw = __expf(lself - m);
    float sinv  = 1.f / (g_s2[n] + selfw + 1e-16f);
    const float* h3n = g_h3 + n * NCLS;
    float acc0 = selfw * h3n[tid];
    float acc1 = (tid < 8) ? selfw * h3n[32 + tid] : 0.f;
    int rs = g_rowstart[n], re = g_rowstart[n + 1];
    int e = rs;
    for (; e + 2 <= re; e += 2) {
        int s0 = g_csr[e], s1 = g_csr[e + 1];
        float a0 = g_alpha2[e], a1 = g_alpha2[e + 1];
        const float* r0 = g_h3 + s0 * NCLS;
        const float* r1 = g_h3 + s1 * NCLS;
        float u0 = r0[tid], u1 = r1[tid];
        float w0 = (tid < 8) ? r0[32 + tid] : 0.f;
        float w1 = (tid < 8) ? r1[32 + tid] : 0.f;
        acc0 = fmaf(a0, u0, acc0); acc0 = fmaf(a1, u1, acc0);
        acc1 = fmaf(a0, w0, acc1); acc1 = fmaf(a1, w1, acc1);
    }
    for (; e < re; e++) {
        int s0 = g_csr[e];
        float a0 = g_alpha2[e];
        acc0 = fmaf(a0, g_h3[s0 * NCLS + tid], acc0);
        if (tid < 8) acc1 = fmaf(a0, g_h3[s0 * NCLS + 32 + tid], acc1);
    }
    acc0 = acc0 * sinv + b2[tid];
    acc1 = (tid < 8) ? acc1 * sinv + b2[32 + tid] : -1e30f;

    // log_softmax over the 40 values held across the warp
    float mx = fmaxf(acc0, acc1);
#pragma unroll
    for (int o = 16; o; o >>= 1) mx = fmaxf(mx, __shfl_xor_sync(0xffffffffu, mx, o));
    float s = __expf(acc0 - mx) + ((tid < 8) ? __expf(acc1 - mx) : 0.f);
#pragma unroll
    for (int o = 16; o; o >>= 1) s += __shfl_xor_sync(0xffffffffu, s, o);
    float lg = logf(s);
    out[n * NCLS + tid] = acc0 - mx - lg;
    if (tid < 8) out[n * NCLS + 32 + tid] = acc1 - mx - lg;
}

// ---------------- launcher ----------------
extern "C" void kernel_launch(void* const* d_in, const int* in_sizes, int n_in,
                              void* d_out, int out_size) {
    const float* x   = (const float*)d_in[0];
    const void*  ei  = d_in[1];
    const float* W1  = (const float*)d_in[2];
    const float* a1s = (const float*)d_in[3];
    const float* a1d = (const float*)d_in[4];
    const float* b1  = (const float*)d_in[5];
    const float* W2  = (const float*)d_in[6];
    const float* a2s = (const float*)d_in[7];
    const float* a2d = (const float*)d_in[8];
    const float* b2  = (const float*)d_in[9];
    float* out = (float*)d_out;

    k_init<<<(NN * NH + 255) / 256, 256>>>(ei);
    k_deg<<<(EE + 255) / 256, 256>>>(ei);
    k_scan<<<1, 1024>>>();
    k_scatter<<<(EE + 255) / 256, 256>>>(ei);
    k_gemm1<<<(NN + 63) / 64, 256>>>(x, W1);
    k_att1<<<NN, 256>>>(a1s, a1d);
    k_emax1<<<(EE + 255) / 256, 256>>>();
    k_esum1<<<(EE + 255) / 256, 256>>>();
    k_gather1<<<NN, 256>>>(b1);
    k_gemm2<<<(NN + 127) / 128, 256>>>(W2, a2s, a2d);
    k_emax2<<<(EE + 255) / 256, 256>>>();
    k_esum2<<<(EE + 255) / 256, 256>>>();
    k_gather2<<<(NN + 3) / 4, 128>>>(b2, out);
}

// round 3
// speedup vs baseline: 1.3650x; 1.2832x over previous
#include <cuda_runtime.h>
#include <math.h>

#define NN 50000
#define EE 800000
#define NF 128
#define NH 8
#define F1 256   // NH*NCH
#define NCLS 40

// ---------------- scratch (static device globals; no allocation) ----------------
__device__ float g_h1[NN * F1];
__device__ float g_h2[NN * F1];
__device__ float g_h3[NN * NCLS];
__device__ float g_a1s[NN * NH];
__device__ float g_a1d[NN * NH];
__device__ float g_a2s[NN];
__device__ float g_a2d[NN];
__device__ int   g_deg[NN];
__device__ int   g_rowstart[NN + 1];
__device__ int   g_cursor[NN];
__device__ int   g_csr[EE];
__device__ int   g_is64;

__device__ __forceinline__ float lrelu(float x) { return x > 0.f ? x : 0.2f * x; }

// ---------------- init: zero degree + detect edge_index dtype ----------------
__global__ void k_init(const void* ei) {
    int i = blockIdx.x * blockDim.x + threadIdx.x;
    if (i < NN) g_deg[i] = 0;
    if (i == 0) {
        const unsigned long long* p = (const unsigned long long*)ei;
        int ok = 1;
        for (int j = 0; j < 64; j++)
            if (p[j] >= (unsigned long long)NN) ok = 0;
        g_is64 = ok;
    }
}

__device__ __forceinline__ int edge_val(const void* ei, long long idx, int is64) {
    return is64 ? (int)((const long long*)ei)[idx] : ((const int*)ei)[idx];
}

// ---------------- CSR build ----------------
__global__ void k_deg(const void* ei) {
    int e = blockIdx.x * blockDim.x + threadIdx.x;
    if (e >= EE) return;
    int d = edge_val(ei, (long long)EE + e, g_is64);
    atomicAdd(&g_deg[d], 1);
}

__global__ void k_scan() {   // single block, 1024 threads
    __shared__ int sh[1024];
    const int ITEMS = 49;    // 1024*49 = 50176 >= NN
    int tid = threadIdx.x;
    int start = tid * ITEMS;
    int lsum = 0;
    for (int i = 0; i < ITEMS; i++) {
        int idx = start + i;
        if (idx < NN) lsum += g_deg[idx];
    }
    sh[tid] = lsum;
    __syncthreads();
    for (int off = 1; off < 1024; off <<= 1) {
        int t = (tid >= off) ? sh[tid - off] : 0;
        __syncthreads();
        sh[tid] += t;
        __syncthreads();
    }
    int run = sh[tid] - lsum;  // exclusive prefix
    for (int i = 0; i < ITEMS; i++) {
        int idx = start + i;
        if (idx < NN) {
            g_rowstart[idx] = run;
            g_cursor[idx]   = run;
            run += g_deg[idx];
        }
    }
    if (tid == 1023) g_rowstart[NN] = sh[1023];
}

__global__ void k_scatter(const void* ei) {
    int e = blockIdx.x * blockDim.x + threadIdx.x;
    if (e >= EE) return;
    int is64 = g_is64;
    int s = edge_val(ei, e, is64);
    int d = edge_val(ei, (long long)EE + e, is64);
    int pos = atomicAdd(&g_cursor[d], 1);
    g_csr[pos] = s;
}

// ---------------- GEMM1: h1 = x @ W1 + fused attention logits ----------------
// block: 64 rows x 256 cols, 256 threads, 8x8 per thread, BK=32
__global__ __launch_bounds__(256) void k_gemm1(const float* __restrict__ x,
                                               const float* __restrict__ W,
                                               const float* __restrict__ asw,
                                               const float* __restrict__ adw) {
    __shared__ float xs[32][65];
    __shared__ float ws[32][256];
    int tid = threadIdx.x;
    int tx = tid & 31, ty = tid >> 5;
    int m0 = blockIdx.x * 64;
    float acc[8][8];
#pragma unroll
    for (int i = 0; i < 8; i++)
#pragma unroll
        for (int j = 0; j < 8; j++) acc[i][j] = 0.f;

    for (int ks = 0; ks < NF; ks += 32) {
        {
            int r  = tid >> 2;
            int c4 = (tid & 3) << 3;
            int gm = m0 + r;
            float4 v0, v1;
            if (gm < NN) {
                const float4* px = (const float4*)(x + (long long)gm * NF + ks + c4);
                v0 = px[0]; v1 = px[1];
            } else {
                v0 = make_float4(0, 0, 0, 0); v1 = v0;
            }
            xs[c4 + 0][r] = v0.x; xs[c4 + 1][r] = v0.y;
            xs[c4 + 2][r] = v0.z; xs[c4 + 3][r] = v0.w;
            xs[c4 + 4][r] = v1.x; xs[c4 + 5][r] = v1.y;
            xs[c4 + 6][r] = v1.z; xs[c4 + 7][r] = v1.w;
        }
#pragma unroll
        for (int it = 0; it < 8; it++) {
            int f4 = it * 256 + tid;
            int k = f4 >> 6, c4 = f4 & 63;
            float4 wv = ((const float4*)(W + (long long)(ks + k) * F1))[c4];
            *((float4*)&ws[k][c4 << 2]) = wv;
        }
        __syncthreads();
#pragma unroll
        for (int k = 0; k < 32; k++) {
            float a[8], b[8];
#pragma unroll
            for (int i = 0; i < 8; i++) a[i] = xs[k][ty + 8 * i];
#pragma unroll
            for (int j = 0; j < 8; j++) b[j] = ws[k][tx + 32 * j];
#pragma unroll
            for (int i = 0; i < 8; i++)
#pragma unroll
                for (int j = 0; j < 8; j++) acc[i][j] = fmaf(a[i], b[j], acc[i][j]);
        }
        __syncthreads();
    }

    // attention weights for this lane's channel (c = tx), per head j
    float was[8], wad[8];
#pragma unroll
    for (int j = 0; j < 8; j++) {
        was[j] = asw[j * 32 + tx];
        wad[j] = adw[j * 32 + tx];
    }

#pragma unroll
    for (int i = 0; i < 8; i++) {
        int gm = m0 + ty + 8 * i;
        if (gm < NN) {
#pragma unroll
            for (int j = 0; j < 8; j++)
                g_h1[gm * F1 + tx + 32 * j] = acc[i][j];
        }
        // fused a1s/a1d: reduce over the 32 channels (lanes) per head
        float vs[8], vd[8];
#pragma unroll
        for (int j = 0; j < 8; j++) {
            vs[j] = acc[i][j] * was[j];
            vd[j] = acc[i][j] * wad[j];
        }
#pragma unroll
        for (int o = 16; o; o >>= 1) {
#pragma unroll
            for (int j = 0; j < 8; j++) {
                vs[j] += __shfl_xor_sync(0xffffffffu, vs[j], o);
                vd[j] += __shfl_xor_sync(0xffffffffu, vd[j], o);
            }
        }
        if (tx == 0 && gm < NN) {
#pragma unroll
            for (int j = 0; j < 8; j++) {
                g_a1s[gm * NH + j] = vs[j];
                g_a1d[gm * NH + j] = vd[j];
            }
        }
    }
}

// ---------------- layer-1: fused softmax + aggregation + bias + ELU ----------------
// one block (256 threads) per node; warp h handles head h, lane = channel
__global__ __launch_bounds__(256) void k_gather1(const float* __restrict__ b1) {
    int n = blockIdx.x;
    int tid = threadIdx.x;
    int h = tid >> 5;          // head, uniform per warp
    float ad = g_a1d[n * NH + h];
    float aself = __expf(lrelu(g_a1s[n * NH + h] + ad));
    float S = aself;
    float acc = aself * g_h1[n * F1 + tid];
    int rs = g_rowstart[n], re = g_rowstart[n + 1];
    int e = rs;
    for (; e + 4 <= re; e += 4) {
        int s0 = g_csr[e], s1 = g_csr[e + 1], s2 = g_csr[e + 2], s3 = g_csr[e + 3];
        float a0 = __expf(lrelu(g_a1s[s0 * NH + h] + ad));
        float a1 = __expf(lrelu(g_a1s[s1 * NH + h] + ad));
        float a2 = __expf(lrelu(g_a1s[s2 * NH + h] + ad));
        float a3 = __expf(lrelu(g_a1s[s3 * NH + h] + ad));
        float v0 = g_h1[s0 * F1 + tid];
        float v1 = g_h1[s1 * F1 + tid];
        float v2 = g_h1[s2 * F1 + tid];
        float v3 = g_h1[s3 * F1 + tid];
        S += a0 + a1 + a2 + a3;
        acc = fmaf(a0, v0, acc);
        acc = fmaf(a1, v1, acc);
        acc = fmaf(a2, v2, acc);
        acc = fmaf(a3, v3, acc);
    }
    for (; e < re; e++) {
        int s = g_csr[e];
        float a = __expf(lrelu(g_a1s[s * NH + h] + ad));
        S += a;
        acc = fmaf(a, g_h1[s * F1 + tid], acc);
    }
    float v = acc * (1.f / (S + 1e-16f)) + b1[tid];
    g_h2[n * F1 + tid] = (v > 0.f) ? v : expm1f(v);
}

// ---------------- GEMM2: h3 = h2 @ W2 + a2 logits ----------------
__global__ __launch_bounds__(256) void k_gemm2(const float* __restrict__ W2,
                                               const float* __restrict__ a2sw,
                                               const float* __restrict__ a2dw) {
    __shared__ float hs[32][129];
    __shared__ float ws2[32][40];
    int tid = threadIdx.x;
    int tx = tid & 7, ty = tid >> 3;
    int m0 = blockIdx.x * 128;
    float acc[4][5];
#pragma unroll
    for (int i = 0; i < 4; i++)
#pragma unroll
        for (int j = 0; j < 5; j++) acc[i][j] = 0.f;

    for (int ks = 0; ks < F1; ks += 32) {
#pragma unroll
        for (int it = 0; it < 4; it++) {
            int f4 = it * 256 + tid;
            int r = f4 >> 3, c4 = f4 & 7;
            int gm = m0 + r;
            float4 v = make_float4(0, 0, 0, 0);
            if (gm < NN) v = *((const float4*)(g_h2 + gm * F1 + ks + (c4 << 2)));
            hs[(c4 << 2) + 0][r] = v.x; hs[(c4 << 2) + 1][r] = v.y;
            hs[(c4 << 2) + 2][r] = v.z; hs[(c4 << 2) + 3][r] = v.w;
        }
#pragma unroll
        for (int it = 0; it < 5; it++) {
            int idx = it * 256 + tid;
            int k = idx / 40, c = idx % 40;
            ws2[k][c] = W2[(ks + k) * NCLS + c];
        }
        __syncthreads();
#pragma unroll
        for (int k = 0; k < 32; k++) {
            float a[4], b[5];
#pragma unroll
            for (int i = 0; i < 4; i++) a[i] = hs[k][ty + 32 * i];
#pragma unroll
            for (int j = 0; j < 5; j++) b[j] = ws2[k][tx + 8 * j];
#pragma unroll
            for (int i = 0; i < 4; i++)
#pragma unroll
                for (int j = 0; j < 5; j++) acc[i][j] = fmaf(a[i], b[j], acc[i][j]);
        }
        __syncthreads();
    }
#pragma unroll
    for (int i = 0; i < 4; i++) {
        int gm = m0 + ty + 32 * i;
        if (gm >= NN) continue;
        float pa = 0.f, pd = 0.f;
#pragma unroll
        for (int j = 0; j < 5; j++) {
            int c = tx + 8 * j;
            g_h3[gm * NCLS + c] = acc[i][j];
            pa = fmaf(acc[i][j], a2sw[c], pa);
            pd = fmaf(acc[i][j], a2dw[c], pd);
        }
#pragma unroll
        for (int o = 4; o; o >>= 1) {
            pa += __shfl_down_sync(0xffffffffu, pa, o, 8);
            pd += __shfl_down_sync(0xffffffffu, pd, o, 8);
        }
        if (tx == 0) {
            g_a2s[gm] = pa;
            g_a2d[gm] = pd;
        }
    }
}

// ---------------- layer-2: fused softmax + gather + bias + log_softmax ----------------
// one warp per node
__global__ __launch_bounds__(128) void k_gather2(const float* __restrict__ b2,
                                                 float* __restrict__ out) {
    int n = blockIdx.x * 4 + (threadIdx.x >> 5);
    if (n >= NN) return;
    int lane = threadIdx.x & 31;
    float adn = g_a2d[n];
    float aself = __expf(lrelu(g_a2s[n] + adn));
    float S = aself;
    const float* h3n = g_h3 + n * NCLS;
    float acc0 = aself * h3n[lane];
    float acc1 = (lane < 8) ? aself * h3n[32 + lane] : 0.f;
    int rs = g_rowstart[n], re = g_rowstart[n + 1];
    int e = rs;
    for (; e + 2 <= re; e += 2) {
        int s0 = g_csr[e], s1 = g_csr[e + 1];
        float a0 = __expf(lrelu(g_a2s[s0] + adn));
        float a1 = __expf(lrelu(g_a2s[s1] + adn));
        const float* r0 = g_h3 + s0 * NCLS;
        const float* r1 = g_h3 + s1 * NCLS;
        float u0 = r0[lane], u1 = r1[lane];
        float w0 = (lane < 8) ? r0[32 + lane] : 0.f;
        float w1 = (lane < 8) ? r1[32 + lane] : 0.f;
        S += a0 + a1;
        acc0 = fmaf(a0, u0, acc0); acc0 = fmaf(a1, u1, acc0);
        acc1 = fmaf(a0, w0, acc1); acc1 = fmaf(a1, w1, acc1);
    }
    for (; e < re; e++) {
        int s0 = g_csr[e];
        float a0 = __expf(lrelu(g_a2s[s0] + adn));
        S += a0;
        acc0 = fmaf(a0, g_h3[s0 * NCLS + lane], acc0);
        if (lane < 8) acc1 = fmaf(a0, g_h3[s0 * NCLS + 32 + lane], acc1);
    }
    float sinv = 1.f / (S + 1e-16f);
    acc0 = acc0 * sinv + b2[lane];
    acc1 = (lane < 8) ? acc1 * sinv + b2[32 + lane] : -1e30f;

    // log_softmax over the 40 values held across the warp
    float mx = fmaxf(acc0, acc1);
#pragma unroll
    for (int o = 16; o; o >>= 1) mx = fmaxf(mx, __shfl_xor_sync(0xffffffffu, mx, o));
    float s = __expf(acc0 - mx) + ((lane < 8) ? __expf(acc1 - mx) : 0.f);
#pragma unroll
    for (int o = 16; o; o >>= 1) s += __shfl_xor_sync(0xffffffffu, s, o);
    float lg = logf(s);
    out[n * NCLS + lane] = acc0 - mx - lg;
    if (lane < 8) out[n * NCLS + 32 + lane] = acc1 - mx - lg;
}

// ---------------- launcher ----------------
extern "C" void kernel_launch(void* const* d_in, const int* in_sizes, int n_in,
                              void* d_out, int out_size) {
    const float* x   = (const float*)d_in[0];
    const void*  ei  = d_in[1];
    const float* W1  = (const float*)d_in[2];
    const float* a1s = (const float*)d_in[3];
    const float* a1d = (const float*)d_in[4];
    const float* b1  = (const float*)d_in[5];
    const float* W2  = (const float*)d_in[6];
    const float* a2s = (const float*)d_in[7];
    const float* a2d = (const float*)d_in[8];
    const float* b2  = (const float*)d_in[9];
    float* out = (float*)d_out;

    k_init<<<(NN + 255) / 256, 256>>>(ei);
    k_deg<<<(EE + 255) / 256, 256>>>(ei);
    k_scan<<<1, 1024>>>();
    k_scatter<<<(EE + 255) / 256, 256>>>(ei);
    k_gemm1<<<(NN + 63) / 64, 256>>>(x, W1, a1s, a1d);
    k_gather1<<<NN, 256>>>(b1);
    k_gemm2<<<(NN + 127) / 128, 256>>>(W2, a2s, a2d);
    k_gather2<<<(NN + 3) / 4, 128>>>(b2, out);
}

// round 4
// speedup vs baseline: 1.4018x; 1.0269x over previous
#include <cuda_runtime.h>
#include <math.h>

#define NN 50000
#define EE 800000
#define NF 128
#define NH 8
#define F1 256   // NH*NCH
#define NCLS 40

__device__ float g_h1[NN * F1];
__device__ float g_h2[NN * F1];
__device__ float g_h3[NN * NCLS];
__device__ float g_a1s[NN * NH];
__device__ float g_a1d[NN * NH];
__device__ float g_a2s[NN];
__device__ float g_a2d[NN];
__device__ int   g_deg[NN];
__device__ int   g_rowstart[NN + 1];
__device__ int   g_cursor[NN];
__device__ int   g_csr[EE];
__device__ int   g_is64;

__device__ __forceinline__ float lrelu(float x) { return x > 0.f ? x : 0.2f * x; }

// ---------------- init: zero degree + detect edge_index dtype ----------------
__global__ void k_init(const void* ei) {
    int i = blockIdx.x * blockDim.x + threadIdx.x;
    if (i < NN) g_deg[i] = 0;
    if (i == 0) {
        const unsigned long long* p = (const unsigned long long*)ei;
        int ok = 1;
        for (int j = 0; j < 64; j++)
            if (p[j] >= (unsigned long long)NN) ok = 0;
        g_is64 = ok;
    }
}

__device__ __forceinline__ int edge_val(const void* ei, long long idx, int is64) {
    return is64 ? (int)((const long long*)ei)[idx] : ((const int*)ei)[idx];
}

// ---------------- CSR build ----------------
__global__ void k_deg(const void* ei) {
    int e = blockIdx.x * blockDim.x + threadIdx.x;
    if (e >= EE) return;
    int d = edge_val(ei, (long long)EE + e, g_is64);
    atomicAdd(&g_deg[d], 1);
}

__global__ void k_scan() {   // single block, 1024 threads
    __shared__ int sh[1024];
    const int ITEMS = 49;
    int tid = threadIdx.x;
    int start = tid * ITEMS;
    int lsum = 0;
    for (int i = 0; i < ITEMS; i++) {
        int idx = start + i;
        if (idx < NN) lsum += g_deg[idx];
    }
    sh[tid] = lsum;
    __syncthreads();
    for (int off = 1; off < 1024; off <<= 1) {
        int t = (tid >= off) ? sh[tid - off] : 0;
        __syncthreads();
        sh[tid] += t;
        __syncthreads();
    }
    int run = sh[tid] - lsum;
    for (int i = 0; i < ITEMS; i++) {
        int idx = start + i;
        if (idx < NN) {
            g_rowstart[idx] = run;
            g_cursor[idx]   = run;
            run += g_deg[idx];
        }
    }
    if (tid == 1023) g_rowstart[NN] = sh[1023];
}

__global__ void k_scatter(const void* ei) {
    int e = blockIdx.x * blockDim.x + threadIdx.x;
    if (e >= EE) return;
    int is64 = g_is64;
    int s = edge_val(ei, e, is64);
    int d = edge_val(ei, (long long)EE + e, is64);
    int pos = atomicAdd(&g_cursor[d], 1);
    g_csr[pos] = s;
}

// ---------------- GEMM1: h1 = x @ W1 + fused attention logits ----------------
__global__ __launch_bounds__(256) void k_gemm1(const float* __restrict__ x,
                                               const float* __restrict__ W,
                                               const float* __restrict__ asw,
                                               const float* __restrict__ adw) {
    __shared__ float xs[32][65];
    __shared__ float ws[32][256];
    int tid = threadIdx.x;
    int tx = tid & 31, ty = tid >> 5;
    int m0 = blockIdx.x * 64;
    float acc[8][8];
#pragma unroll
    for (int i = 0; i < 8; i++)
#pragma unroll
        for (int j = 0; j < 8; j++) acc[i][j] = 0.f;

    for (int ks = 0; ks < NF; ks += 32) {
        {
            int r  = tid >> 2;
            int c4 = (tid & 3) << 3;
            int gm = m0 + r;
            float4 v0, v1;
            if (gm < NN) {
                const float4* px = (const float4*)(x + (long long)gm * NF + ks + c4);
                v0 = px[0]; v1 = px[1];
            } else {
                v0 = make_float4(0, 0, 0, 0); v1 = v0;
            }
            xs[c4 + 0][r] = v0.x; xs[c4 + 1][r] = v0.y;
            xs[c4 + 2][r] = v0.z; xs[c4 + 3][r] = v0.w;
            xs[c4 + 4][r] = v1.x; xs[c4 + 5][r] = v1.y;
            xs[c4 + 6][r] = v1.z; xs[c4 + 7][r] = v1.w;
        }
#pragma unroll
        for (int it = 0; it < 8; it++) {
            int f4 = it * 256 + tid;
            int k = f4 >> 6, c4 = f4 & 63;
            float4 wv = ((const float4*)(W + (long long)(ks + k) * F1))[c4];
            *((float4*)&ws[k][c4 << 2]) = wv;
        }
        __syncthreads();
#pragma unroll
        for (int k = 0; k < 32; k++) {
            float a[8], b[8];
#pragma unroll
            for (int i = 0; i < 8; i++) a[i] = xs[k][ty + 8 * i];
#pragma unroll
            for (int j = 0; j < 8; j++) b[j] = ws[k][tx + 32 * j];
#pragma unroll
            for (int i = 0; i < 8; i++)
#pragma unroll
                for (int j = 0; j < 8; j++) acc[i][j] = fmaf(a[i], b[j], acc[i][j]);
        }
        __syncthreads();
    }

    float was[8], wad[8];
#pragma unroll
    for (int j = 0; j < 8; j++) {
        was[j] = asw[j * 32 + tx];
        wad[j] = adw[j * 32 + tx];
    }

#pragma unroll
    for (int i = 0; i < 8; i++) {
        int gm = m0 + ty + 8 * i;
        if (gm < NN) {
#pragma unroll
            for (int j = 0; j < 8; j++)
                g_h1[gm * F1 + tx + 32 * j] = acc[i][j];
        }
        float vs[8], vd[8];
#pragma unroll
        for (int j = 0; j < 8; j++) {
            vs[j] = acc[i][j] * was[j];
            vd[j] = acc[i][j] * wad[j];
        }
#pragma unroll
        for (int o = 16; o; o >>= 1) {
#pragma unroll
            for (int j = 0; j < 8; j++) {
                vs[j] += __shfl_xor_sync(0xffffffffu, vs[j], o);
                vd[j] += __shfl_xor_sync(0xffffffffu, vd[j], o);
            }
        }
        if (tx == 0 && gm < NN) {
#pragma unroll
            for (int j = 0; j < 8; j++) {
                g_a1s[gm * NH + j] = vs[j];
                g_a1d[gm * NH + j] = vd[j];
            }
        }
    }
}

// ---------------- layer-1: fused softmax + aggregation + bias + ELU ----------------
// block = node (8 warps); warp = head; lanes in 4 groups of 8; group g -> edge e+g;
// each lane holds a float4 of channels -> one LDG.128 covers 4 edges x 128B.
__global__ __launch_bounds__(256) void k_gather1(const float* __restrict__ b1) {
    int n = blockIdx.x;
    int tid = threadIdx.x;
    int h = tid >> 5;
    int lane = tid & 31;
    int g = lane >> 3, l = lane & 7;
    int gbase = g << 3;
    int off = h * 32 + l * 4;
    float ad = g_a1d[n * NH + h];
    float4 acc = make_float4(0.f, 0.f, 0.f, 0.f);
    float S = 0.f;
    if (g == 0) {   // self-loop handled by group 0
        float aself = __expf(lrelu(g_a1s[n * NH + h] + ad));
        float4 v = *(const float4*)(g_h1 + n * F1 + off);
        acc.x = aself * v.x; acc.y = aself * v.y;
        acc.z = aself * v.z; acc.w = aself * v.w;
        S = aself;
    }
    int rs = g_rowstart[n], re = g_rowstart[n + 1];
    for (int e = rs; e < re; e += 4) {
        bool act = (e + g) < re;
        int s = 0; float a = 0.f;
        if (l == 0 && act) {
            s = g_csr[e + g];
            a = __expf(lrelu(g_a1s[s * NH + h] + ad));
        }
        s = __shfl_sync(0xffffffffu, s, gbase);
        a = __shfl_sync(0xffffffffu, a, gbase);
        if (act) {
            float4 v = *(const float4*)(g_h1 + s * F1 + off);
            acc.x = fmaf(a, v.x, acc.x);
            acc.y = fmaf(a, v.y, acc.y);
            acc.z = fmaf(a, v.z, acc.z);
            acc.w = fmaf(a, v.w, acc.w);
            S += a;
        }
    }
    // reduce the 4 groups (lanes differing in bits 3..4 hold the same channels)
#pragma unroll
    for (int o = 8; o <= 16; o <<= 1) {
        acc.x += __shfl_xor_sync(0xffffffffu, acc.x, o);
        acc.y += __shfl_xor_sync(0xffffffffu, acc.y, o);
        acc.z += __shfl_xor_sync(0xffffffffu, acc.z, o);
        acc.w += __shfl_xor_sync(0xffffffffu, acc.w, o);
        S     += __shfl_xor_sync(0xffffffffu, S, o);
    }
    if (g == 0) {
        float sinv = 1.f / (S + 1e-16f);
        float4 bb = *(const float4*)(b1 + off);
        float4 r;
        r.x = acc.x * sinv + bb.x;
        r.y = acc.y * sinv + bb.y;
        r.z = acc.z * sinv + bb.z;
        r.w = acc.w * sinv + bb.w;
        r.x = (r.x > 0.f) ? r.x : expm1f(r.x);
        r.y = (r.y > 0.f) ? r.y : expm1f(r.y);
        r.z = (r.z > 0.f) ? r.z : expm1f(r.z);
        r.w = (r.w > 0.f) ? r.w : expm1f(r.w);
        *(float4*)(g_h2 + n * F1 + off) = r;
    }
}

// ---------------- GEMM2: h3 = h2 @ W2 + a2 logits ----------------
__global__ __launch_bounds__(256) void k_gemm2(const float* __restrict__ W2,
                                               const float* __restrict__ a2sw,
                                               const float* __restrict__ a2dw) {
    __shared__ float hs[32][129];
    __shared__ float ws2[32][40];
    int tid = threadIdx.x;
    int tx = tid & 7, ty = tid >> 3;
    int m0 = blockIdx.x * 128;
    float acc[4][5];
#pragma unroll
    for (int i = 0; i < 4; i++)
#pragma unroll
        for (int j = 0; j < 5; j++) acc[i][j] = 0.f;

    for (int ks = 0; ks < F1; ks += 32) {
#pragma unroll
        for (int it = 0; it < 4; it++) {
            int f4 = it * 256 + tid;
            int r = f4 >> 3, c4 = f4 & 7;
            int gm = m0 + r;
            float4 v = make_float4(0, 0, 0, 0);
            if (gm < NN) v = *((const float4*)(g_h2 + gm * F1 + ks + (c4 << 2)));
            hs[(c4 << 2) + 0][r] = v.x; hs[(c4 << 2) + 1][r] = v.y;
            hs[(c4 << 2) + 2][r] = v.z; hs[(c4 << 2) + 3][r] = v.w;
        }
#pragma unroll
        for (int it = 0; it < 5; it++) {
            int idx = it * 256 + tid;
            int k = idx / 40, c = idx % 40;
            ws2[k][c] = W2[(ks + k) * NCLS + c];
        }
        __syncthreads();
#pragma unroll
        for (int k = 0; k < 32; k++) {
            float a[4], b[5];
#pragma unroll
            for (int i = 0; i < 4; i++) a[i] = hs[k][ty + 32 * i];
#pragma unroll
            for (int j = 0; j < 5; j++) b[j] = ws2[k][tx + 8 * j];
#pragma unroll
            for (int i = 0; i < 4; i++)
#pragma unroll
                for (int j = 0; j < 5; j++) acc[i][j] = fmaf(a[i], b[j], acc[i][j]);
        }
        __syncthreads();
    }
#pragma unroll
    for (int i = 0; i < 4; i++) {
        int gm = m0 + ty + 32 * i;
        if (gm >= NN) continue;
        float pa = 0.f, pd = 0.f;
#pragma unroll
        for (int j = 0; j < 5; j++) {
            int c = tx + 8 * j;
            g_h3[gm * NCLS + c] = acc[i][j];
            pa = fmaf(acc[i][j], a2sw[c], pa);
            pd = fmaf(acc[i][j], a2dw[c], pd);
        }
#pragma unroll
        for (int o = 4; o; o >>= 1) {
            pa += __shfl_down_sync(0xffffffffu, pa, o, 8);
            pd += __shfl_down_sync(0xffffffffu, pd, o, 8);
        }
        if (tx == 0) {
            g_a2s[gm] = pa;
            g_a2d[gm] = pd;
        }
    }
}

// ---------------- layer-2: fused softmax + gather + bias + log_softmax ----------------
// one warp per node; lanes 0..19 hold 40 channels as float2; csr/a2s batched 4-wide.
__global__ __launch_bounds__(128) void k_gather2(const float* __restrict__ b2,
                                                 float* __restrict__ out) {
    int n = blockIdx.x * 4 + (threadIdx.x >> 5);
    if (n >= NN) return;
    int lane = threadIdx.x & 31;
    bool actc = lane < 20;
    float adn = g_a2d[n];
    float aself = __expf(lrelu(g_a2s[n] + adn));
    float S = aself;
    float2 acc = make_float2(0.f, 0.f);
    if (actc) {
        float2 v = *(const float2*)(g_h3 + n * NCLS + lane * 2);
        acc.x = aself * v.x; acc.y = aself * v.y;
    }
    int rs = g_rowstart[n], re = g_rowstart[n + 1];
    for (int e = rs; e < re; e += 4) {
        int s = 0; float a = 0.f;
        if (lane < 4 && e + lane < re) {
            s = g_csr[e + lane];
            a = __expf(lrelu(g_a2s[s] + adn));
        }
#pragma unroll
        for (int j = 0; j < 4; j++) {
            if (e + j >= re) break;
            int sj   = __shfl_sync(0xffffffffu, s, j);
            float aj = __shfl_sync(0xffffffffu, a, j);
            S += aj;
            if (actc) {
                float2 v = *(const float2*)(g_h3 + sj * NCLS + lane * 2);
                acc.x = fmaf(aj, v.x, acc.x);
                acc.y = fmaf(aj, v.y, acc.y);
            }
        }
    }
    float sinv = 1.f / (S + 1e-16f);
    float vx = -1e30f, vy = -1e30f;
    if (actc) {
        float2 bb = *(const float2*)(b2 + lane * 2);
        vx = acc.x * sinv + bb.x;
        vy = acc.y * sinv + bb.y;
    }
    float mx = fmaxf(vx, vy);
#pragma unroll
    for (int o = 16; o; o >>= 1) mx = fmaxf(mx, __shfl_xor_sync(0xffffffffu, mx, o));
    float s2 = actc ? (__expf(vx - mx) + __expf(vy - mx)) : 0.f;
#pragma unroll
    for (int o = 16; o; o >>= 1) s2 += __shfl_xor_sync(0xffffffffu, s2, o);
    float lg = logf(s2);
    if (actc) {
        float2 r; r.x = vx - mx - lg; r.y = vy - mx - lg;
        *(float2*)(out + n * NCLS + lane * 2) = r;
    }
}

// ---------------- launcher ----------------
extern "C" void kernel_launch(void* const* d_in, const int* in_sizes, int n_in,
                              void* d_out, int out_size) {
    const float* x   = (const float*)d_in[0];
    const void*  ei  = d_in[1];
    const float* W1  = (const float*)d_in[2];
    const float* a1s = (const float*)d_in[3];
    const float* a1d = (const float*)d_in[4];
    const float* b1  = (const float*)d_in[5];
    const float* W2  = (const float*)d_in[6];
    const float* a2s = (const float*)d_in[7];
    const float* a2d = (const float*)d_in[8];
    const float* b2  = (const float*)d_in[9];
    float* out = (float*)d_out;

    k_init<<<(NN + 255) / 256, 256>>>(ei);
    k_deg<<<(EE + 255) / 256, 256>>>(ei);
    k_scan<<<1, 1024>>>();
    k_scatter<<<(EE + 255) / 256, 256>>>(ei);
    k_gemm1<<<(NN + 63) / 64, 256>>>(x, W1, a1s, a1d);
    k_gather1<<<NN, 256>>>(b1);
    k_gemm2<<<(NN + 127) / 128, 256>>>(W2, a2s, a2d);
    k_gather2<<<(NN + 3) / 4, 128>>>(b2, out);
}